// round 17
// baseline (speedup 1.0000x reference)
#include <cuda_runtime.h>
#include <cuda_fp16.h>
#include <math.h>
#include <stdint.h>

#define EMB   1024
#define NH    16
#define HD    64
#define SEQ   2048
#define BATCH 2
#define MROWS (BATCH*SEQ)     // 4096
#define QKVN  (3*EMB)         // 3072
#define EPS   1.1920929e-07f

// ---- scratch (no allocations allowed) ----
__device__ __half g_nrm_h[(size_t)MROWS*EMB];
__device__ __half g_att_h[(size_t)MROWS*EMB];
__device__ __half g_wqkv_h[(size_t)QKVN*EMB];
__device__ __half g_wo_h[(size_t)EMB*EMB];
__device__ __half g_qh[(size_t)BATCH*NH*SEQ*HD];
__device__ __half g_kh[(size_t)BATCH*NH*SEQ*HD];
__device__ __half g_v[(size_t)MROWS*EMB];
__device__ __half g_vth[(size_t)BATCH*NH*HD*SEQ];

// ============================================================
// helpers
// ============================================================
__device__ __forceinline__ uint32_t smem_u32(const void* p) {
    uint32_t a;
    asm("{ .reg .u64 t; cvta.to.shared.u64 t, %1; cvt.u32.u64 %0, t; }" : "=r"(a) : "l"(p));
    return a;
}
__device__ __forceinline__ void mma_f16(float* c, const uint32_t* a,
                                        uint32_t b0, uint32_t b1) {
    asm volatile(
        "mma.sync.aligned.m16n8k16.row.col.f32.f16.f16.f32 "
        "{%0,%1,%2,%3}, {%4,%5,%6,%7}, {%8,%9}, {%0,%1,%2,%3};"
        : "+f"(c[0]), "+f"(c[1]), "+f"(c[2]), "+f"(c[3])
        : "r"(a[0]), "r"(a[1]), "r"(a[2]), "r"(a[3]), "r"(b0), "r"(b1));
}
__device__ __forceinline__ void cp16(uint32_t sdst, const void* gsrc) {
    asm volatile("cp.async.cg.shared.global [%0], [%1], 16;" :: "r"(sdst), "l"(gsrc));
}
#define CP_COMMIT() asm volatile("cp.async.commit_group;")
#define CP_WAIT1()  asm volatile("cp.async.wait_group 1;")
#define CP_WAIT0()  asm volatile("cp.async.wait_group 0;")

// ============================================================
// weight fp16 conversion
// ============================================================
__global__ __launch_bounds__(256) void conv_hi_kernel(
    const float* __restrict__ x, __half* __restrict__ hi)
{
    int i = blockIdx.x * 256 + threadIdx.x;
    float4 v = ((const float4*)x)[i];
    __half2 h01 = __floats2half2_rn(v.x, v.y);
    __half2 h23 = __floats2half2_rn(v.z, v.w);
    uint2 hp;
    hp.x = *(uint32_t*)&h01; hp.y = *(uint32_t*)&h23;
    *(uint2*)(hi + (size_t)i*4) = hp;
}

// ============================================================
// shared GEMM mainloop: 128x128 tile, K-chunk 64,
// 3-stage cp.async ring, ONE syncthreads per chunk, 2 CTAs/SM
// ============================================================
#define STRW  36                      // words (u32) per smem row (72 halfs)
#define TWA   (128*STRW)
#define BUFW  (2*TWA)                 // one stage: Ah + Bh
#define OFF_AH 0
#define OFF_BH TWA
#define GEMM_SMEM (3*BUFW*4)          // 110592 bytes

#define GEMM_MAINLOOP(ACC) \
    auto issue = [&](int ch) { \
        int k0 = ch * 64; \
        uint32_t bufw = (uint32_t)(ch % 3) * BUFW; \
        _Pragma("unroll") \
        for (int i = 0; i < 8; i++) { \
            int task = tid + i * 256; \
            int piece = task >> 10; \
            int rem = task & 1023; \
            int row = rem >> 3, seg = rem & 7; \
            const __half* src = (piece ? Bh : Ah) + (size_t)((piece ? n0 : m0) + row)*1024 + k0 + seg*8; \
            uint32_t sa = sbase + (bufw + (piece ? OFF_BH : OFF_AH) + row*STRW + seg*4)*4; \
            cp16(sa, src); \
        } \
        CP_COMMIT(); \
    }; \
    issue(0); \
    issue(1); \
    for (int ch = 0; ch < 16; ch++) { \
        if (ch < 15) { CP_WAIT1(); } \
        else         { CP_WAIT0(); } \
        __syncthreads(); \
        if (ch + 2 < 16) issue(ch + 2); \
        uint32_t bufw = (uint32_t)(ch % 3) * BUFW; \
        const uint32_t* AsH = sg + bufw + OFF_AH; \
        const uint32_t* BsH = sg + bufw + OFF_BH; \
        _Pragma("unroll") \
        for (int s = 0; s < 4; s++) { \
            uint32_t aH[2][4]; \
            _Pragma("unroll") \
            for (int mt = 0; mt < 2; mt++) { \
                int o = (wm*32 + mt*16 + g)*STRW + s*8 + t4; \
                aH[mt][0] = AsH[o];           aH[mt][1] = AsH[o + 8*STRW]; \
                aH[mt][2] = AsH[o + 4];       aH[mt][3] = AsH[o + 8*STRW + 4]; \
            } \
            _Pragma("unroll") \
            for (int nt = 0; nt < 8; nt++) { \
                int o = (wn*64 + nt*8 + g)*STRW + s*8 + t4; \
                uint32_t bh0 = BsH[o], bh1 = BsH[o + 4]; \
                _Pragma("unroll") \
                for (int mt = 0; mt < 2; mt++) \
                    mma_f16(ACC[mt][nt], aH[mt], bh0, bh1); \
            } \
        } \
    }

// ============================================================
// QKV GEMM with fused RoPE/scale/layout epilogue
// ============================================================
__global__ __launch_bounds__(256, 2) void gemm_qkv_kernel(
    const __half* __restrict__ Ah, const __half* __restrict__ Bh,
    const float* __restrict__ cosb, const float* __restrict__ sinb,
    __half* __restrict__ qh, __half* __restrict__ kh, __half* __restrict__ vv)
{
    extern __shared__ __align__(16) uint32_t sg[];
    uint32_t sbase = smem_u32(sg);
    int tid = threadIdx.x;
    int m0 = blockIdx.y * 128, n0 = blockIdx.x * 128;
    int lane = tid & 31, wid = tid >> 5;
    int g = lane >> 2, t4 = lane & 3;
    int wm = wid & 3, wn = wid >> 2;

    float acc[2][8][4];
    #pragma unroll
    for (int mt = 0; mt < 2; mt++)
        #pragma unroll
        for (int nt = 0; nt < 8; nt++)
            #pragma unroll
            for (int r = 0; r < 4; r++) acc[mt][nt][r] = 0.0f;

    GEMM_MAINLOOP(acc)

    int region = n0 >> 10;                    // 0=q, 1=k, 2=v
    int colbase = (n0 & 1023) + wn*64;
    if (region < 2) {
        int h = colbase >> 6;
        __half* dst = region ? kh : qh;
        float scale = region ? 1.0f : 0.125f;
        #pragma unroll
        for (int mt = 0; mt < 2; mt++) {
            #pragma unroll
            for (int rr = 0; rr < 2; rr++) {
                int m = m0 + wm*32 + mt*16 + g + rr*8;
                int s = m & (SEQ - 1), b = m >> 11;
                size_t base = ((size_t)(b*NH + h)*SEQ + s)*HD;
                const float* cb = cosb + s*HD;
                const float* sb = sinb + s*HD;
                #pragma unroll
                for (int nt = 0; nt < 4; nt++) {
                    int d = nt*8 + t4*2;
                    float x0 = acc[mt][nt][rr*2+0],   x1 = acc[mt][nt][rr*2+1];
                    float y0 = acc[mt][nt+4][rr*2+0], y1 = acc[mt][nt+4][rr*2+1];
                    float2 cd = *(const float2*)(cb + d);
                    float2 sd = *(const float2*)(sb + d);
                    float2 ce = *(const float2*)(cb + d + 32);
                    float2 se = *(const float2*)(sb + d + 32);
                    float r0v = (cd.x*x0 + sd.x*y0)*scale;
                    float r1v = (cd.y*x1 + sd.y*y1)*scale;
                    float e0v = (ce.x*y0 + se.x*x0)*scale;
                    float e1v = (ce.y*y1 + se.y*x1)*scale;
                    __half2 hd = __floats2half2_rn(r0v, r1v);
                    __half2 he = __floats2half2_rn(e0v, e1v);
                    *(uint32_t*)(dst + base + d)      = *(uint32_t*)&hd;
                    *(uint32_t*)(dst + base + d + 32) = *(uint32_t*)&he;
                }
            }
        }
    } else {
        #pragma unroll
        for (int mt = 0; mt < 2; mt++) {
            int r0 = m0 + wm*32 + mt*16 + g;
            #pragma unroll
            for (int nt = 0; nt < 8; nt++) {
                int o = colbase + nt*8 + t4*2;
                __half2 h0 = __floats2half2_rn(acc[mt][nt][0], acc[mt][nt][1]);
                __half2 h1 = __floats2half2_rn(acc[mt][nt][2], acc[mt][nt][3]);
                *(uint32_t*)(vv + (size_t)r0*EMB + o)     = *(uint32_t*)&h0;
                *(uint32_t*)(vv + (size_t)(r0+8)*EMB + o) = *(uint32_t*)&h1;
            }
        }
    }
}

// ============================================================
// out-proj GEMM (+ residual)
// ============================================================
__global__ __launch_bounds__(256, 2) void gemm_f16_kernel(
    const __half* __restrict__ Ah, const __half* __restrict__ Bh,
    const float* __restrict__ Res, float* __restrict__ C, int N)
{
    extern __shared__ __align__(16) uint32_t sg[];
    uint32_t sbase = smem_u32(sg);
    int tid = threadIdx.x;
    int m0 = blockIdx.y * 128, n0 = blockIdx.x * 128;
    int lane = tid & 31, wid = tid >> 5;
    int g = lane >> 2, t4 = lane & 3;
    int wm = wid & 3, wn = wid >> 2;

    float acc[2][8][4];
    #pragma unroll
    for (int mt = 0; mt < 2; mt++)
        #pragma unroll
        for (int nt = 0; nt < 8; nt++)
            #pragma unroll
            for (int r = 0; r < 4; r++) acc[mt][nt][r] = 0.0f;

    GEMM_MAINLOOP(acc)

    #pragma unroll
    for (int mt = 0; mt < 2; mt++) {
        int r0 = m0 + wm*32 + mt*16 + g;
        int r1 = r0 + 8;
        #pragma unroll
        for (int nt = 0; nt < 8; nt++) {
            int col = n0 + wn*64 + nt*8 + t4*2;
            float2 v0 = make_float2(acc[mt][nt][0], acc[mt][nt][1]);
            float2 v1 = make_float2(acc[mt][nt][2], acc[mt][nt][3]);
            float2 q0 = *(const float2*)(Res + (size_t)r0*N + col);
            float2 q1 = *(const float2*)(Res + (size_t)r1*N + col);
            v0.x += q0.x; v0.y += q0.y;
            v1.x += q1.x; v1.y += q1.y;
            *(float2*)(C + (size_t)r0*N + col) = v0;
            *(float2*)(C + (size_t)r1*N + col) = v1;
        }
    }
}

// ============================================================
// RMSNorm -> fp16
// ============================================================
__global__ __launch_bounds__(256) void rmsnorm_kernel(
    const float* __restrict__ x, const float* __restrict__ w,
    __half* __restrict__ out_h)
{
    int row = blockIdx.x;
    int tid = threadIdx.x;
    const float4* xr = (const float4*)(x + (size_t)row*EMB);
    float4 v = xr[tid];
    float ss = v.x*v.x + v.y*v.y + v.z*v.z + v.w*v.w;
    #pragma unroll
    for (int o = 16; o > 0; o >>= 1) ss += __shfl_xor_sync(0xffffffffu, ss, o);
    __shared__ float wsum[8];
    if ((tid & 31) == 0) wsum[tid >> 5] = ss;
    __syncthreads();
    if (tid < 8) {
        float t = wsum[tid];
        #pragma unroll
        for (int o = 4; o > 0; o >>= 1) t += __shfl_xor_sync(0xffu, t, o);
        if (tid == 0) wsum[0] = t;
    }
    __syncthreads();
    float inv = rsqrtf(wsum[0] * (1.0f/EMB) + EPS);
    float4 wv = ((const float4*)w)[tid];
    __half2 h01 = __floats2half2_rn(v.x*inv*wv.x, v.y*inv*wv.y);
    __half2 h23 = __floats2half2_rn(v.z*inv*wv.z, v.w*inv*wv.w);
    uint2 hp;
    hp.x = *(uint32_t*)&h01; hp.y = *(uint32_t*)&h23;
    *(uint2*)(out_h + (size_t)row*EMB + tid*4) = hp;
}

// ============================================================
// prep_v: fp16 transpose V -> [bh][d][s]
// ============================================================
__global__ __launch_bounds__(256) void prep_v_kernel(
    const __half* __restrict__ vv, __half* __restrict__ vth)
{
    __shared__ __half ts[64*72];
    int st = blockIdx.x * 64, h = blockIdx.y, b = blockIdx.z;
    int tid = threadIdx.x;
    int row = tid >> 2, seg = tid & 3;
    const __half* src = vv + (size_t)(b*SEQ + st + row)*EMB + h*HD + seg*16;
    uint4 u0 = *(const uint4*)(src);
    uint4 u1 = *(const uint4*)(src + 8);
    *(uint4*)&ts[row*72 + seg*16]     = u0;
    *(uint4*)&ts[row*72 + seg*16 + 8] = u1;
    __syncthreads();
    int d = tid >> 2, ss = tid & 3;
    __half hv[16];
    #pragma unroll
    for (int j = 0; j < 16; j++)
        hv[j] = ts[(ss*16 + j)*72 + d];
    size_t ob = ((size_t)((b*NH + h)*HD) + d)*SEQ + st + ss*16;
    *(uint4*)(vth + ob)     = *(uint4*)&hv[0];
    *(uint4*)(vth + ob + 8) = *(uint4*)&hv[8];
}

// ============================================================
// Tensor-core causal flash attention
//  single-pass fp16, 3-stage KV ring, one barrier/tile, 2 CTAs/SM
// ============================================================
#define QROWS 128
#define KSTRW 36
#define QSZW  (QROWS*KSTRW)
#define KSZW  (64*KSTRW)
#define F_Q   0
#define F_K0  QSZW                       // + buf*KSZW (3 bufs)
#define F_V0  (QSZW + 3*KSZW)            // + buf*KSZW (3 bufs)
#define FLASH_SMEM ((QSZW + 6*KSZW)*4)   // 73728 bytes

__global__ __launch_bounds__(256, 2) void flash_mma_kernel(
    const __half* __restrict__ Qh, const __half* __restrict__ Kh,
    const __half* __restrict__ Vth, __half* __restrict__ attn_h)
{
    extern __shared__ __align__(16) uint32_t sf[];
    uint32_t sbase = smem_u32(sf);
    int tid = threadIdx.x, lane = tid & 31, wid = tid >> 5;
    int g = lane >> 2, t4 = lane & 3;
    int qt = (gridDim.x - 1) - blockIdx.x;
    int h = blockIdx.y, b = blockIdx.z;
    int bh = b*NH + h;
    int q0 = qt * QROWS;
    int nkt = 2*(qt + 1);

    const __half* gQh = Qh  + (size_t)bh*SEQ*HD;
    const __half* gKh = Kh  + (size_t)bh*SEQ*HD;
    const __half* gVh = Vth + (size_t)bh*HD*SEQ;

    auto issueKV = [&](int kt) {
        int k0 = kt * 64;
        uint32_t bufw = (uint32_t)(kt % 3) * KSZW;
        #pragma unroll
        for (int i = 0; i < 2; i++) {
            int task = tid + i*256;
            int row = task >> 3, seg = task & 7;
            const __half* src = gKh + (size_t)(k0 + row)*HD + seg*8;
            uint32_t dst = sbase + ((F_K0 + bufw) + row*KSTRW + seg*4)*4;
            cp16(dst, src);
        }
        #pragma unroll
        for (int i = 0; i < 2; i++) {
            int task = tid + i*256;
            int row = task >> 3, seg = task & 7;
            const __half* src = gVh + (size_t)row*SEQ + k0 + seg*8;
            uint32_t dst = sbase + ((F_V0 + bufw) + row*KSTRW + seg*4)*4;
            cp16(dst, src);
        }
        CP_COMMIT();
    };

    // prologue: Q + KV0 (group 0), KV1 (group 1)
    #pragma unroll
    for (int i = 0; i < 4; i++) {
        int task = tid + i*256;
        int row = task >> 3, seg = task & 7;
        const __half* src = gQh + (size_t)(q0 + row)*HD + seg*8;
        uint32_t dst = sbase + (F_Q + row*KSTRW + seg*4)*4;
        cp16(dst, src);
    }
    issueKV(0);          // commits group 0 (Q + KV0)
    issueKV(1);          // group 1

    float m0 = -INFINITY, m1 = -INFINITY, l0 = 0.f, l1 = 0.f;
    float o[8][4];
    #pragma unroll
    for (int dt = 0; dt < 8; dt++)
        #pragma unroll
        for (int e = 0; e < 4; e++) o[dt][e] = 0.f;

    const uint32_t* QhS = sf + F_Q;
    int qrow = (wid*16 + g) * KSTRW;

    for (int kt = 0; kt < nkt; kt++) {
        if (kt < nkt - 1) { CP_WAIT1(); }
        else              { CP_WAIT0(); }
        __syncthreads();
        if (kt + 2 < nkt) issueKV(kt + 2);

        uint32_t bufw = (uint32_t)(kt % 3) * KSZW;
        const uint32_t* KhS = sf + F_K0 + bufw;
        const uint32_t* VhS = sf + F_V0 + bufw;

        float sc[8][4];
        #pragma unroll
        for (int nt = 0; nt < 8; nt++)
            #pragma unroll
            for (int e = 0; e < 4; e++) sc[nt][e] = 0.f;

        #pragma unroll
        for (int s = 0; s < 4; s++) {
            int qo = qrow + s*8 + t4;
            uint32_t aH[4] = { QhS[qo], QhS[qo + 8*KSTRW], QhS[qo + 4], QhS[qo + 8*KSTRW + 4] };
            #pragma unroll
            for (int nt = 0; nt < 8; nt++) {
                int ko = (nt*8 + g)*KSTRW + s*8 + t4;
                mma_f16(sc[nt], aH, KhS[ko], KhS[ko + 4]);
            }
        }

        if (kt >= 2*qt) {
            int cb = kt*64;
            int r0 = q0 + wid*16 + g, r1 = r0 + 8;
            #pragma unroll
            for (int nt = 0; nt < 8; nt++) {
                int c0 = cb + nt*8 + 2*t4;
                if (c0     > r0) sc[nt][0] = -INFINITY;
                if (c0 + 1 > r0) sc[nt][1] = -INFINITY;
                if (c0     > r1) sc[nt][2] = -INFINITY;
                if (c0 + 1 > r1) sc[nt][3] = -INFINITY;
            }
        }

        float mt0 = -INFINITY, mt1 = -INFINITY;
        #pragma unroll
        for (int nt = 0; nt < 8; nt++) {
            mt0 = fmaxf(mt0, fmaxf(sc[nt][0], sc[nt][1]));
            mt1 = fmaxf(mt1, fmaxf(sc[nt][2], sc[nt][3]));
        }
        mt0 = fmaxf(mt0, __shfl_xor_sync(0xffffffffu, mt0, 1));
        mt0 = fmaxf(mt0, __shfl_xor_sync(0xffffffffu, mt0, 2));
        mt1 = fmaxf(mt1, __shfl_xor_sync(0xffffffffu, mt1, 1));
        mt1 = fmaxf(mt1, __shfl_xor_sync(0xffffffffu, mt1, 2));
        float mn0 = fmaxf(m0, mt0), mn1 = fmaxf(m1, mt1);
        float corr0 = __expf(m0 - mn0), corr1 = __expf(m1 - mn1);
        m0 = mn0; m1 = mn1;

        float ls0 = 0.f, ls1 = 0.f;
        uint32_t phA[8], phB[8];
        #pragma unroll
        for (int nt = 0; nt < 8; nt++) {
            float p0 = __expf(sc[nt][0] - mn0);
            float p1 = __expf(sc[nt][1] - mn0);
            float p2 = __expf(sc[nt][2] - mn1);
            float p3 = __expf(sc[nt][3] - mn1);
            ls0 += p0 + p1;  ls1 += p2 + p3;
            __half2 hA = __floats2half2_rn(p0, p1);
            __half2 hB = __floats2half2_rn(p2, p3);
            phA[nt] = *(uint32_t*)&hA;
            phB[nt] = *(uint32_t*)&hB;
        }
        ls0 += __shfl_xor_sync(0xffffffffu, ls0, 1);
        ls0 += __shfl_xor_sync(0xffffffffu, ls0, 2);
        ls1 += __shfl_xor_sync(0xffffffffu, ls1, 1);
        ls1 += __shfl_xor_sync(0xffffffffu, ls1, 2);
        l0 = l0*corr0 + ls0;
        l1 = l1*corr1 + ls1;
        #pragma unroll
        for (int dt = 0; dt < 8; dt++) {
            o[dt][0] *= corr0; o[dt][1] *= corr0;
            o[dt][2] *= corr1; o[dt][3] *= corr1;
        }

        #pragma unroll
        for (int kk = 0; kk < 4; kk++) {
            uint32_t aH[4] = { phA[2*kk], phB[2*kk], phA[2*kk+1], phB[2*kk+1] };
            #pragma unroll
            for (int dt = 0; dt < 8; dt++) {
                int vo = (dt*8 + g)*KSTRW + kk*8 + t4;
                mma_f16(o[dt], aH, VhS[vo], VhS[vo + 4]);
            }
        }
    }

    float il0 = 1.0f / l0, il1 = 1.0f / l1;
    int r0g = b*SEQ + q0 + wid*16 + g;
    int r1g = r0g + 8;
    int cbase = h*HD;
    #pragma unroll
    for (int dt = 0; dt < 8; dt++) {
        int c = cbase + dt*8 + 2*t4;
        __half2 ha = __floats2half2_rn(o[dt][0]*il0, o[dt][1]*il0);
        __half2 hb = __floats2half2_rn(o[dt][2]*il1, o[dt][3]*il1);
        *(uint32_t*)(attn_h + (size_t)r0g*EMB + c) = *(uint32_t*)&ha;
        *(uint32_t*)(attn_h + (size_t)r1g*EMB + c) = *(uint32_t*)&hb;
    }
}

// ============================================================
// launch
// ============================================================
extern "C" void kernel_launch(void* const* d_in, const int* in_sizes, int n_in,
                              void* d_out, int out_size)
{
    const float* emb  = (const float*)d_in[0];
    const float* cosb = (const float*)d_in[1];
    const float* sinb = (const float*)d_in[2];
    const float* nw   = (const float*)d_in[3];
    const float* qkvw = (const float*)d_in[4];
    const float* ow   = (const float*)d_in[5];
    float* out = (float*)d_out;

    __half *nh, *ah, *wqh, *woh, *qh, *kh, *vv, *vth;
    cudaGetSymbolAddress((void**)&nh,  g_nrm_h);
    cudaGetSymbolAddress((void**)&ah,  g_att_h);
    cudaGetSymbolAddress((void**)&wqh, g_wqkv_h);
    cudaGetSymbolAddress((void**)&woh, g_wo_h);
    cudaGetSymbolAddress((void**)&qh,  g_qh);
    cudaGetSymbolAddress((void**)&kh,  g_kh);
    cudaGetSymbolAddress((void**)&vv,  g_v);
    cudaGetSymbolAddress((void**)&vth, g_vth);

    cudaFuncSetAttribute(gemm_qkv_kernel,
        cudaFuncAttributeMaxDynamicSharedMemorySize, GEMM_SMEM);
    cudaFuncSetAttribute(gemm_f16_kernel,
        cudaFuncAttributeMaxDynamicSharedMemorySize, GEMM_SMEM);
    cudaFuncSetAttribute(flash_mma_kernel,
        cudaFuncAttributeMaxDynamicSharedMemorySize, FLASH_SMEM);

    conv_hi_kernel<<<(QKVN*EMB/4)/256, 256>>>(qkvw, wqh);
    conv_hi_kernel<<<(EMB*EMB/4)/256, 256>>>(ow, woh);
    rmsnorm_kernel<<<MROWS, 256>>>(emb, nw, nh);
    gemm_qkv_kernel<<<dim3(QKVN/128, MROWS/128), 256, GEMM_SMEM>>>(
        nh, wqh, cosb, sinb, qh, kh, vv);
    prep_v_kernel<<<dim3(SEQ/64, NH, BATCH), 256>>>(vv, vth);
    flash_mma_kernel<<<dim3(SEQ/QROWS, NH, BATCH), 256, FLASH_SMEM>>>(
        qh, kh, vth, ah);
    gemm_f16_kernel<<<dim3(EMB/128, MROWS/128), 256, GEMM_SMEM>>>(
        ah, woh, emb, out, EMB);
}